// round 14
// baseline (speedup 1.0000x reference)
#include <cuda_runtime.h>
#include <stdint.h>

#define NUM_CLASSES 100000
#define EMBED_DIM   512
#define BATCH       16384
#define NWORDS      (NUM_CLASSES / 32)   // 3125 copy blocks (one word = 32 rows)
#define NUPD        BATCH

// Self-cleaning scratch (zero-initialized by CUDA; every call restores zeros).
__device__ unsigned g_touched[NWORDS];   // bit set => class touched this call
__device__ int g_head[NUM_CLASSES];      // idx+1 of chain head, 0 = empty
__device__ int g_next[BATCH];            // idx+1 of next in chain, 0 = end

// ---------------------------------------------------------------------------
// K1: build per-class chains + touched bitmask + zero loss slot
// ---------------------------------------------------------------------------
__global__ void build_kernel(const int* __restrict__ labels,
                             float* __restrict__ out) {
    int i = blockIdx.x * blockDim.x + threadIdx.x;
    if (i == 0) out[0] = 0.0f;
    if (i < BATCH) {
        int l = labels[i];
        g_next[i] = atomicExch(&g_head[l], i + 1);
        atomicOr(&g_touched[l >> 5], 1u << (l & 31));
    }
}

// ---------------------------------------------------------------------------
// K2 (fused): blocks [0, NUPD) update touched rows + loss (latency-bound,
// dispatched FIRST so their dependent-load chains overlap the copy stream);
// blocks [NUPD, NUPD+NWORDS) stream-copy untouched rows (32 rows/block).
// Writes are disjoint; scratch is self-cleaned for the next call.
// ---------------------------------------------------------------------------
__global__ __launch_bounds__(128)
void fused_kernel(const float* __restrict__ features,
                  const int* __restrict__ labels,
                  const float* __restrict__ center_var,
                  float* __restrict__ out) {   // out[0]=loss, out+1=centers
    const int t = threadIdx.x;
    float* outc = out + 1;

    if (blockIdx.x < NUPD) {
        // ---------------- update path: one block per chain head ------------
        const int i = blockIdx.x;
        const int l = labels[i];
        if (g_head[l] != i + 1) return;  // uniform; only chain head works

        const float4* crow =
            reinterpret_cast<const float4*>(center_var + (size_t)l * EMBED_DIM);
        float4 c = crow[t];

        float4 fs = make_float4(0.f, 0.f, 0.f, 0.f);
        float lossp = 0.f;
        int n = 0;

        // walk duplicate chain (length 1 for ~98% of touched classes)
        for (int j = i + 1; j != 0; j = g_next[j - 1]) {
            const float4* frow =
                reinterpret_cast<const float4*>(features + (size_t)(j - 1) * EMBED_DIM);
            float4 f = frow[t];
            float dx = f.x - c.x, dy = f.y - c.y, dz = f.z - c.z, dw = f.w - c.w;
            lossp += dx * dx + dy * dy + dz * dz + dw * dw;
            fs.x += f.x; fs.y += f.y; fs.z += f.z; fs.w += f.w;
            n++;
        }

        // new = c + 0.05 * (sum_f - n*c)
        const float a = 0.05f;
        const float fn = (float)n;
        __shared__ float srow[EMBED_DIM];
        srow[4 * t + 0] = c.x + a * (fs.x - fn * c.x);
        srow[4 * t + 1] = c.y + a * (fs.y - fn * c.y);
        srow[4 * t + 2] = c.z + a * (fs.z - fn * c.z);
        srow[4 * t + 3] = c.w + a * (fs.w - fn * c.w);
        __syncthreads();

        float* orow = outc + (size_t)l * EMBED_DIM;
        if (t < 127) {
            *reinterpret_cast<float4*>(orow + 3 + 4 * t) =
                make_float4(srow[4 * t + 3], srow[4 * t + 4],
                            srow[4 * t + 5], srow[4 * t + 6]);
        } else {
            orow[0] = srow[0]; orow[1] = srow[1]; orow[2] = srow[2];
            orow[511] = srow[511];
        }

        // block-reduce loss, single atomic per chain; self-clean head
        #pragma unroll
        for (int off = 16; off > 0; off >>= 1)
            lossp += __shfl_down_sync(0xFFFFFFFFu, lossp, off);
        __shared__ float ws[4];
        if ((t & 31) == 0) ws[t >> 5] = lossp;
        __syncthreads();
        if (t == 0) {
            const float inv_n = 1.0f / ((float)BATCH * (float)EMBED_DIM);
            atomicAdd(out, (ws[0] + ws[1] + ws[2] + ws[3]) * inv_n);
            g_head[l] = 0;               // self-clean for next call
        }
    } else {
        // ---------------- copy path: 32 contiguous rows per block ----------
        const int word = blockIdx.x - NUPD;
        const unsigned w = g_touched[word];
        __syncthreads();                 // all threads have read w
        if (t == 0) g_touched[word] = 0; // self-clean (exclusive owner)

        const int base = word * 32;
        #pragma unroll 4
        for (int r = 0; r < 32; r++) {
            if (w & (1u << r)) continue;         // update path owns this row
            const int row = base + r;
            const float4* src =
                reinterpret_cast<const float4*>(center_var + (size_t)row * EMBED_DIM);
            float* dst = outc + (size_t)row * EMBED_DIM;
            float4 a4 = src[t];
            if (t < 127) {
                float4 b4 = src[t + 1];          // L1-hit overlap
                *reinterpret_cast<float4*>(dst + 3 + 4 * t) =
                    make_float4(a4.w, b4.x, b4.y, b4.z);   // 16B-aligned store
            } else {
                float4 h = src[0];               // L1 hit (lane 0's line)
                dst[0] = h.x; dst[1] = h.y; dst[2] = h.z;
                dst[511] = a4.w;                 // a4 = floats 508..511
            }
        }
    }
}

// ---------------------------------------------------------------------------
// Launch
// ---------------------------------------------------------------------------
extern "C" void kernel_launch(void* const* d_in, const int* in_sizes, int n_in,
                              void* d_out, int out_size) {
    const float* features   = (const float*)d_in[0];
    const int*   labels     = (const int*)d_in[1];
    const float* center_var = (const float*)d_in[2];
    float* out = (float*)d_out;

    build_kernel<<<(BATCH + 255) / 256, 256>>>(labels, out);
    fused_kernel<<<NUPD + NWORDS, 128>>>(features, labels, center_var, out);
}

// round 15
// speedup vs baseline: 1.1159x; 1.1159x over previous
#include <cuda_runtime.h>
#include <stdint.h>

#define NUM_CLASSES 100000
#define EMBED_DIM   512
#define BATCH       16384
#define NBUILD      64                    // build blocks inside K1
#define NCOPYB      6144                  // flat copy blocks in K1
#define TOTF        (NUM_CLASSES * (size_t)EMBED_DIM)   // 51,200,000 floats
#define NGROUPS     ((TOTF - 4) / 4)      // 12,799,999 aligned float4 groups

// Self-cleaning scratch (zero-initialized; every call restores zeros).
__device__ int g_head[NUM_CLASSES];      // idx+1 of chain head, 0 = empty
__device__ int g_next[BATCH];            // idx+1 of next in chain, 0 = end

// ---------------------------------------------------------------------------
// K1: build blocks [0,NBUILD) build chains + zero loss; the rest flat-copy
// ALL of center_var into out+1 (branch-free, globally aligned stores).
// ---------------------------------------------------------------------------
__global__ __launch_bounds__(256)
void copy_build_kernel(const int* __restrict__ labels,
                       const float* __restrict__ center_var,
                       float* __restrict__ out) {
    const int t = threadIdx.x;

    if (blockIdx.x < NBUILD) {
        // ----- build: 16384 items over 64 blocks x 256 threads -------------
        int i = blockIdx.x * 256 + t;
        if (i == 0) {
            out[0] = 0.0f;                          // loss slot
            // edge floats of the copy (head 3 + tail 1)
            const float4 h = *reinterpret_cast<const float4*>(center_var);
            out[1] = h.x; out[2] = h.y; out[3] = h.z;
            out[TOTF] = center_var[TOTF - 1];
        }
        if (i < BATCH) {
            int l = labels[i];
            g_next[i] = atomicExch(&g_head[l], i + 1);
        }
        return;
    }

    // ----- flat copy: group g covers src floats [4g+3, 4g+6] ---------------
    // dst = out+1+3+4g is 16B-aligned (out is 16B-aligned).
    const float4* s4 = reinterpret_cast<const float4*>(center_var);
    float* outc = out + 1;

    size_t g = (size_t)(blockIdx.x - NBUILD) * 256 + t;
    const size_t stride = (size_t)NCOPYB * 256;

    #pragma unroll 4
    for (; g < NGROUPS; g += stride) {
        float4 a = s4[g];
        float4 b = s4[g + 1];                       // L1-hit overlap
        *reinterpret_cast<float4*>(outc + 3 + 4 * g) =
            make_float4(a.w, b.x, b.y, b.z);
    }
}

// ---------------------------------------------------------------------------
// K2: update touched rows (overwrite the copied values) + loss.
// One block per batch item; only chain heads work. Plain stores (K1 done).
// ---------------------------------------------------------------------------
__global__ __launch_bounds__(128)
void update_kernel(const float* __restrict__ features,
                   const int* __restrict__ labels,
                   const float* __restrict__ center_var,
                   float* __restrict__ out) {
    const int t = threadIdx.x;
    const int i = blockIdx.x;
    const int l = labels[i];
    if (g_head[l] != i + 1) return;      // uniform; only chain head works
    float* outc = out + 1;

    const float4* crow =
        reinterpret_cast<const float4*>(center_var + (size_t)l * EMBED_DIM);
    float4 c = crow[t];

    float4 fs = make_float4(0.f, 0.f, 0.f, 0.f);
    float lossp = 0.f;
    int n = 0;

    for (int j = i + 1; j != 0; j = g_next[j - 1]) {
        const float4* frow =
            reinterpret_cast<const float4*>(features + (size_t)(j - 1) * EMBED_DIM);
        float4 f = frow[t];
        float dx = f.x - c.x, dy = f.y - c.y, dz = f.z - c.z, dw = f.w - c.w;
        lossp += dx * dx + dy * dy + dz * dz + dw * dw;
        fs.x += f.x; fs.y += f.y; fs.z += f.z; fs.w += f.w;
        n++;
    }

    // new = c + 0.05 * (sum_f - n*c)
    const float a = 0.05f;
    const float fn = (float)n;
    __shared__ float srow[EMBED_DIM];
    srow[4 * t + 0] = c.x + a * (fs.x - fn * c.x);
    srow[4 * t + 1] = c.y + a * (fs.y - fn * c.y);
    srow[4 * t + 2] = c.z + a * (fs.z - fn * c.z);
    srow[4 * t + 3] = c.w + a * (fs.w - fn * c.w);
    __syncthreads();

    float* orow = outc + (size_t)l * EMBED_DIM;
    if (t < 127) {
        *reinterpret_cast<float4*>(orow + 3 + 4 * t) =
            make_float4(srow[4 * t + 3], srow[4 * t + 4],
                        srow[4 * t + 5], srow[4 * t + 6]);
    } else {
        orow[0] = srow[0]; orow[1] = srow[1]; orow[2] = srow[2];
        orow[511] = srow[511];
    }

    // block-reduce loss, single atomic per chain; self-clean head
    #pragma unroll
    for (int off = 16; off > 0; off >>= 1)
        lossp += __shfl_down_sync(0xFFFFFFFFu, lossp, off);
    __shared__ float ws[4];
    if ((t & 31) == 0) ws[t >> 5] = lossp;
    __syncthreads();
    if (t == 0) {
        const float inv_n = 1.0f / ((float)BATCH * (float)EMBED_DIM);
        atomicAdd(out, (ws[0] + ws[1] + ws[2] + ws[3]) * inv_n);
        g_head[l] = 0;                   // self-clean for next call
    }
}

// ---------------------------------------------------------------------------
// Launch
// ---------------------------------------------------------------------------
extern "C" void kernel_launch(void* const* d_in, const int* in_sizes, int n_in,
                              void* d_out, int out_size) {
    const float* features   = (const float*)d_in[0];
    const int*   labels     = (const int*)d_in[1];
    const float* center_var = (const float*)d_in[2];
    float* out = (float*)d_out;

    copy_build_kernel<<<NBUILD + NCOPYB, 256>>>(labels, center_var, out);
    update_kernel<<<BATCH, 128>>>(features, labels, center_var, out);
}